// round 1
// baseline (speedup 1.0000x reference)
#include <cuda_runtime.h>

// StatsQuantizer 4-bit fake-quant, 8192x8192 fp32.
// Forward math (gradient-only terms eliminated):
//   s    = 2 * mean(|w_row|)                          (per row, axis=1)
//   c    = clamp(w/s, -clip/2, clip/2 - 1e-6)
//   out  = s * ((rint(c*8 - 0.5) + 0.5) / 8)
//
// One CTA per row; row (32 KB) lives in registers across the block
// reduction so the weight is read exactly once. Pure HBM-bound:
// 512 MiB total traffic.

#define ROWS 8192
#define COLS 8192
#define TPB  256
#define V4_PER_THREAD (COLS / 4 / TPB)   // 8 float4 per thread

__global__ __launch_bounds__(TPB, 4)
void stats_quant_kernel(const float* __restrict__ w,
                        const float* __restrict__ clip_val,
                        float* __restrict__ out) {
    const int row = blockIdx.x;
    const float4* __restrict__ wrow =
        reinterpret_cast<const float4*>(w + (size_t)row * COLS);
    float4* __restrict__ orow =
        reinterpret_cast<float4*>(out + (size_t)row * COLS);

    // ---- Load full row slice into registers, accumulate |w| ----
    float4 v[V4_PER_THREAD];
    float asum = 0.0f;
#pragma unroll
    for (int i = 0; i < V4_PER_THREAD; i++) {
        v[i] = wrow[threadIdx.x + i * TPB];
        asum += fabsf(v[i].x) + fabsf(v[i].y) + fabsf(v[i].z) + fabsf(v[i].w);
    }

    // ---- Block reduction: warp shfl then cross-warp via smem ----
    __shared__ float warp_sums[TPB / 32];
    __shared__ float s_scale;
#pragma unroll
    for (int off = 16; off > 0; off >>= 1)
        asum += __shfl_xor_sync(0xffffffffu, asum, off);
    if ((threadIdx.x & 31) == 0)
        warp_sums[threadIdx.x >> 5] = asum;
    __syncthreads();
    if (threadIdx.x == 0) {
        float t = 0.0f;
#pragma unroll
        for (int i = 0; i < TPB / 32; i++) t += warp_sums[i];
        // s = 2 * (t / 8192) = t / 4096
        s_scale = t * (1.0f / 4096.0f);
    }
    __syncthreads();

    const float s    = s_scale;
    const float invs = 1.0f / s;            // full-precision rcp, once
    const float hc   = 0.5f * clip_val[0];  // clip/2
    const float lo   = -hc;
    const float hi   = hc - 1e-6f;
    const float sdiv8 = s * 0.125f;

    // ---- Quantize from registers, write back ----
#pragma unroll
    for (int i = 0; i < V4_PER_THREAD; i++) {
        float4 r;
        float* pv = &v[i].x;
        float* pr = &r.x;
#pragma unroll
        for (int j = 0; j < 4; j++) {
            float c  = fminf(fmaxf(pv[j] * invs, lo), hi);
            float b4 = fmaf(c, 8.0f, -0.5f);
            pr[j]    = (rintf(b4) + 0.5f) * sdiv8;
        }
        orow[threadIdx.x + i * TPB] = r;
    }
}

extern "C" void kernel_launch(void* const* d_in, const int* in_sizes, int n_in,
                              void* d_out, int out_size) {
    const float* weight   = (const float*)d_in[0];
    const float* clip_val = (const float*)d_in[1];
    float* out            = (float*)d_out;
    (void)in_sizes; (void)n_in; (void)out_size;

    stats_quant_kernel<<<ROWS, TPB>>>(weight, clip_val, out);
}

// round 2
// speedup vs baseline: 1.0129x; 1.0129x over previous
#include <cuda_runtime.h>

// StatsQuantizer 4-bit fake-quant, 8192x8192 fp32.
// Forward math (gradient-only terms eliminated):
//   s    = 2 * mean(|w_row|)          (per row, axis=1)
//   c    = clamp(w/s, -clip/2, clip/2 - 1e-6)
//   out  = s * ((rint(c*8 - 0.5) + 0.5) / 8)
//
// One CTA per row. Row staged in SMEM (not registers) across the block
// reduction -> low register count -> smem-limited occupancy (~6 CTAs/SM)
// keeps the HBM pipe full while other CTAs sit at the barrier.
// Streaming cache hints: data is touched exactly once each way.

#define ROWS 8192
#define COLS 8192
#define TPB  256
#define V4_PER_THREAD (COLS / 4 / TPB)   // 8 float4 per thread

__global__ __launch_bounds__(TPB)
void stats_quant_kernel(const float* __restrict__ w,
                        const float* __restrict__ clip_val,
                        float* __restrict__ out) {
    __shared__ float4 srow[COLS / 4];        // 32 KB
    __shared__ float warp_sums[TPB / 32];
    __shared__ float s_scale;

    const int row = blockIdx.x;
    const float4* __restrict__ wrow =
        reinterpret_cast<const float4*>(w + (size_t)row * COLS);
    float4* __restrict__ orow =
        reinterpret_cast<float4*>(out + (size_t)row * COLS);

    // ---- Stream row global -> smem, accumulate |w| on the fly ----
    float asum = 0.0f;
#pragma unroll
    for (int i = 0; i < V4_PER_THREAD; i++) {
        const int idx = threadIdx.x + i * TPB;
        float4 v = __ldcs(&wrow[idx]);       // evict-first: no reuse in L2
        srow[idx] = v;
        asum += fabsf(v.x) + fabsf(v.y) + fabsf(v.z) + fabsf(v.w);
    }

    // ---- Block reduction: warp shfl then cross-warp via smem ----
#pragma unroll
    for (int off = 16; off > 0; off >>= 1)
        asum += __shfl_xor_sync(0xffffffffu, asum, off);
    if ((threadIdx.x & 31) == 0)
        warp_sums[threadIdx.x >> 5] = asum;
    __syncthreads();
    if (threadIdx.x == 0) {
        float t = 0.0f;
#pragma unroll
        for (int i = 0; i < TPB / 32; i++) t += warp_sums[i];
        // s = 2 * (t / 8192) = t / 4096
        s_scale = t * (1.0f / 4096.0f);
    }
    __syncthreads();

    const float s     = s_scale;
    const float invs  = 1.0f / s;
    const float hc    = 0.5f * clip_val[0];
    const float lo    = -hc;
    const float hi    = hc - 1e-6f;
    const float sdiv8 = s * 0.125f;

    // ---- Quantize from smem, stream out ----
#pragma unroll
    for (int i = 0; i < V4_PER_THREAD; i++) {
        const int idx = threadIdx.x + i * TPB;
        float4 v = srow[idx];
        float4 r;
        float* pv = &v.x;
        float* pr = &r.x;
#pragma unroll
        for (int j = 0; j < 4; j++) {
            float c  = fminf(fmaxf(pv[j] * invs, lo), hi);
            float b4 = fmaf(c, 8.0f, -0.5f);
            pr[j]    = (rintf(b4) + 0.5f) * sdiv8;
        }
        __stcs(&orow[idx], r);               // evict-first store
    }
}

extern "C" void kernel_launch(void* const* d_in, const int* in_sizes, int n_in,
                              void* d_out, int out_size) {
    const float* weight   = (const float*)d_in[0];
    const float* clip_val = (const float*)d_in[1];
    float* out            = (float*)d_out;
    (void)in_sizes; (void)n_in; (void)out_size;

    stats_quant_kernel<<<ROWS, TPB>>>(weight, clip_val, out);
}